// round 16
// baseline (speedup 1.0000x reference)
#include <cuda_runtime.h>
#include <cuda_fp16.h>
#include <math.h>
#include <stdint.h>

// Problem constants
#define B   128
#define P   196
#define E   2048
#define AA  512
#define EMB 512
#define D   512
#define V   10000
#define LCD 128
#define TCAP 26
#define T   25
#define XDIM (EMB + E + LCD)   // 2688
#define G4  (4*D)              // 2048
#define NCAT (AA + E + G4)     // 4608

// partial-buffer layout: hgemm S=4 over NCAT at base; W_ih S=12 at XOFF
#define HS   4
#define XS   12
#define XOFF ((size_t)HS*B*NCAT)
#define PART_TOTAL (XOFF + (size_t)XS*B*G4)

// Output layout: predictions (B,T,V), caps (B,TCAP), dec_len (B,), alphas (B,T,P), sort_ind (B,)
#define OFF_PRED   ((size_t)0)
#define OFF_CAPS   ((size_t)B*T*V)
#define OFF_DECLEN (OFF_CAPS + (size_t)B*TCAP)
#define OFF_ALPHAS (OFF_DECLEN + (size_t)B)
#define OFF_SORT   (OFF_ALPHAS + (size_t)B*T*P)

// ------------------- scratch -------------------
__device__ float  g_att1[(size_t)B*P*AA];
__device__ __half g_ench[(size_t)B*P*E];
__device__ float  g_Wcat[(size_t)D*NCAT];
__device__ float  g_part[PART_TOTAL];
__device__ float  g_mean[B*E];
__device__ float  g_h[B*D];
__device__ float  g_c[B*D];
__device__ float  g_hnew[B*D];
__device__ float  g_alpha[B*P];
__device__ float  g_x[B*XDIM];
__device__ int    g_sort[B];
__device__ int    g_declen[B];

// ------------------- sort + small outputs + style into x -------------------
__global__ void k_sort(const int* __restrict__ caps_in,
                       const int* __restrict__ cap_len,
                       const int* __restrict__ length_class,
                       const float* __restrict__ lc_table,
                       float* __restrict__ out)
{
    __shared__ int cls[B];
    int i = threadIdx.x;
    cls[i] = cap_len[i];
    __syncthreads();
    int my = cls[i];
    int rank = 0;
    for (int j = 0; j < B; j++) {
        int cj = cls[j];
        if (cj > my || (cj == my && j < i)) rank++;
    }
    g_sort[rank] = i;
    __syncthreads();
    int si = g_sort[i];
    int dl = cls[si] - 1;
    g_declen[i] = dl;
    out[OFF_DECLEN + i] = (float)dl;
    out[OFF_SORT + i]   = (float)si;
    for (int tt = 0; tt < TCAP; tt++)
        out[OFF_CAPS + (size_t)i*TCAP + tt] = (float)caps_in[si*TCAP + tt];
    int lcidx = length_class[si];
    for (int j = 0; j < LCD; j++)
        g_x[(size_t)i*XDIM + EMB + j] = lc_table[lcidx*LCD + j];
}

// ------------------- fused: mean over pixels + sorted fp16 copy -------------------
__global__ void k_prep(const float* __restrict__ enc)
{
    int b = blockIdx.y;
    int e = blockIdx.x * 256 + threadIdx.x;
    const float* base = enc + (size_t)g_sort[b]*P*E + e;
    __half* hbase = g_ench + (size_t)b*P*E + e;
    float s = 0.f;
    #pragma unroll 4
    for (int p = 0; p < P; p++) {
        float v = base[(size_t)p*E];
        s += v;
        hbase[(size_t)p*E] = __float2half_rn(v);
    }
    g_mean[b*E + e] = s * (1.0f / (float)P);
}

// ------------------- concat weights -------------------
__global__ void k_concatW(const float* __restrict__ Wdec,
                          const float* __restrict__ Wfb,
                          const float* __restrict__ Whh)
{
    int idx = blockIdx.x * 256 + threadIdx.x;
    if (idx >= D * NCAT) return;
    int k = idx / NCAT, n = idx % NCAT;
    float v;
    if (n < AA)            v = Wdec[k*AA + n];
    else if (n < AA + E)   v = Wfb[k*E + (n - AA)];
    else                   v = Whh[k*G4 + (n - AA - E)];
    g_Wcat[idx] = v;
}

// =================== common GEMM defs ===================
#define MM_BM 128
#define MM_BN 64
#define MM_BK 16
#define MM_PAD 4
#define SROW (MM_BK + MM_PAD)
#define SIDX(r,k) ((r)*SROW + (k))
#define STAGE_U32 ((MM_BM + MM_BN) * SROW * 2)   // tf32 hi+lo stage = 7680 u32
#define DSMEM_BYTES (2 * STAGE_U32 * 4)          // 61440

// fp16 stage: [row][8 half2 pairs], padded row = 12 u32 (48B, 16B-aligned)
#define SROW16 12
#define SIDX16(r,kp) ((r)*SROW16 + (kp))
#define STAGE16_U32 ((MM_BM + MM_BN) * SROW16)   // 2304 u32
#define DSMEM16_BYTES (2 * STAGE16_U32 * 4)      // 18432

struct GP {
    const float* A; int lda;
    const float* W; int ldw;
    float* C; int ldc;
    int M, N, Kc;
    const int* rowmap; int rowdiv;
    const float* bias;
    const int* declen; int tstep;
    int prec;
    int nbx;   // x-blocks for 1D decomposition in combo
};

__device__ __forceinline__ uint32_t f2tf32(float x) {
    uint32_t u;
    asm("cvt.rna.tf32.f32 %0, %1;" : "=r"(u) : "f"(x));
    return u;
}
__device__ __forceinline__ void mma_tf32(float* c, const uint32_t* a, const uint32_t* b) {
    asm volatile("mma.sync.aligned.m16n8k8.row.col.f32.tf32.tf32.f32 "
                 "{%0,%1,%2,%3}, {%4,%5,%6,%7}, {%8,%9}, {%0,%1,%2,%3};"
                 : "+f"(c[0]), "+f"(c[1]), "+f"(c[2]), "+f"(c[3])
                 : "r"(a[0]), "r"(a[1]), "r"(a[2]), "r"(a[3]),
                   "r"(b[0]), "r"(b[1]));
}
__device__ __forceinline__ void mma_f16(float* c, const uint32_t* a, const uint32_t* b) {
    asm volatile("mma.sync.aligned.m16n8k16.row.col.f32.f16.f16.f32 "
                 "{%0,%1,%2,%3}, {%4,%5,%6,%7}, {%8,%9}, {%0,%1,%2,%3};"
                 : "+f"(c[0]), "+f"(c[1]), "+f"(c[2]), "+f"(c[3])
                 : "r"(a[0]), "r"(a[1]), "r"(a[2]), "r"(a[3]),
                   "r"(b[0]), "r"(b[1]));
}

extern __shared__ uint32_t dynsh[];

// ---------- epilogue shared by both bodies ----------
__device__ __forceinline__ void gemm_epilogue(float c[4][2][4], int bm, int bn, int bz,
                                              int wm, int wn, int lane, const GP& p)
{
    if (p.bias) {
        #pragma unroll
        for (int i = 0; i < 4; i++) {
            int r0 = bm + wm * 64 + i * 16 + (lane >> 2);
            float rs0 = p.declen ? ((p.tstep < p.declen[r0])     ? 1.f : 0.f) : 1.f;
            float rs8 = p.declen ? ((p.tstep < p.declen[r0 + 8]) ? 1.f : 0.f) : 1.f;
            #pragma unroll
            for (int j = 0; j < 2; j++) {
                int cc = bn + wn * 16 + j * 8 + (lane & 3) * 2;
                if (cc < p.N) {
                    float b0 = p.bias[cc], b1 = p.bias[cc + 1];
                    *(float2*)&p.C[(size_t)r0 * p.ldc + cc] =
                        make_float2((c[i][j][0] + b0) * rs0, (c[i][j][1] + b1) * rs0);
                    *(float2*)&p.C[(size_t)(r0+8) * p.ldc + cc] =
                        make_float2((c[i][j][2] + b0) * rs8, (c[i][j][3] + b1) * rs8);
                }
            }
        }
    } else {
        float* pout = p.C + (size_t)bz * p.M * p.N;
        #pragma unroll
        for (int i = 0; i < 4; i++) {
            int r0 = bm + wm * 64 + i * 16 + (lane >> 2);
            #pragma unroll
            for (int j = 0; j < 2; j++) {
                int cc = bn + wn * 16 + j * 8 + (lane & 3) * 2;
                if (cc < p.N) {
                    *(float2*)&pout[(size_t)r0 * p.ldc + cc]     = make_float2(c[i][j][0], c[i][j][1]);
                    *(float2*)&pout[(size_t)(r0+8) * p.ldc + cc] = make_float2(c[i][j][2], c[i][j][3]);
                }
            }
        }
    }
}

// =================== TF32 body (double-buffered; prec = 3-term hi/lo) ===============
__device__ __forceinline__ void mma_body(int bx, int by, int bz, const GP& p)
{
    int tid = threadIdx.x;
    int lane = tid & 31, wid = tid >> 5;
    int wm = wid & 1, wn = wid >> 1;
    int bn = bx * MM_BN;
    int bm = by * MM_BM;
    int kbase = bz * p.Kc;

    int a_m = tid >> 1, a_k = (tid & 1) * 8;
    int gm = bm + a_m;
    int arow = gm;
    if (p.rowmap) { int bb = gm / p.rowdiv; int pp = gm - bb * p.rowdiv; arow = p.rowmap[bb] * p.rowdiv + pp; }
    const float* aptr = p.A + (size_t)arow * p.lda + kbase + a_k;
    int w_k = tid >> 4, w_n = (tid & 15) * 4;
    const float* wptr = p.W + (size_t)(kbase + w_k) * p.ldw + bn + w_n;
    bool wok = (bn + w_n) < p.N;

    float c[4][2][4];
    #pragma unroll
    for (int i = 0; i < 4; i++)
        #pragma unroll
        for (int j = 0; j < 2; j++)
            #pragma unroll
            for (int q = 0; q < 4; q++) c[i][j][q] = 0.f;

    int iters = p.Kc / MM_BK;
    float4 pa0 = *(const float4*)(aptr);
    float4 pa1 = *(const float4*)(aptr + 4);
    float4 pw  = wok ? *(const float4*)(wptr) : make_float4(0,0,0,0);

    for (int it = 0; it < iters; it++) {
        uint32_t* stage = dynsh + (it & 1) * STAGE_U32;
        uint32_t* sA  = stage;
        uint32_t* sW  = sA + MM_BM * SROW;
        uint32_t* sAl = sW + MM_BN * SROW;
        uint32_t* sWl = sAl + MM_BM * SROW;

        {
            float av[8] = {pa0.x,pa0.y,pa0.z,pa0.w,pa1.x,pa1.y,pa1.z,pa1.w};
            uint32_t hi[8];
            #pragma unroll
            for (int q = 0; q < 8; q++) hi[q] = f2tf32(av[q]);
            *(uint4*)&sA[SIDX(a_m, a_k)]     = *(uint4*)&hi[0];
            *(uint4*)&sA[SIDX(a_m, a_k + 4)] = *(uint4*)&hi[4];
            uint32_t wh[4] = {f2tf32(pw.x), f2tf32(pw.y), f2tf32(pw.z), f2tf32(pw.w)};
            sW[SIDX(w_n+0, w_k)] = wh[0]; sW[SIDX(w_n+1, w_k)] = wh[1];
            sW[SIDX(w_n+2, w_k)] = wh[2]; sW[SIDX(w_n+3, w_k)] = wh[3];
            if (p.prec) {
                uint32_t lo[8];
                #pragma unroll
                for (int q = 0; q < 8; q++) lo[q] = f2tf32(av[q] - __uint_as_float(hi[q]));
                *(uint4*)&sAl[SIDX(a_m, a_k)]     = *(uint4*)&lo[0];
                *(uint4*)&sAl[SIDX(a_m, a_k + 4)] = *(uint4*)&lo[4];
                sWl[SIDX(w_n+0, w_k)] = f2tf32(pw.x - __uint_as_float(wh[0]));
                sWl[SIDX(w_n+1, w_k)] = f2tf32(pw.y - __uint_as_float(wh[1]));
                sWl[SIDX(w_n+2, w_k)] = f2tf32(pw.z - __uint_as_float(wh[2]));
                sWl[SIDX(w_n+3, w_k)] = f2tf32(pw.w - __uint_as_float(wh[3]));
            }
        }
        __syncthreads();

        if (it + 1 < iters) {
            const float* an = aptr + (it + 1) * MM_BK;
            pa0 = *(const float4*)(an);
            pa1 = *(const float4*)(an + 4);
            pw  = wok ? *(const float4*)(wptr + (size_t)(it + 1) * MM_BK * p.ldw)
                      : make_float4(0,0,0,0);
        }

        #pragma unroll
        for (int ks = 0; ks < 2; ks++) {
            int krow = ks * 8 + (lane & 3);
            uint32_t afr[4][4], bfr[2][2];
            #pragma unroll
            for (int i = 0; i < 4; i++) {
                int r = wm * 64 + i * 16 + (lane >> 2);
                afr[i][0] = sA[SIDX(r, krow)];
                afr[i][1] = sA[SIDX(r + 8, krow)];
                afr[i][2] = sA[SIDX(r, krow + 4)];
                afr[i][3] = sA[SIDX(r + 8, krow + 4)];
            }
            #pragma unroll
            for (int j = 0; j < 2; j++) {
                int cc = wn * 16 + j * 8 + (lane >> 2);
                bfr[j][0] = sW[SIDX(cc, krow)];
                bfr[j][1] = sW[SIDX(cc, krow + 4)];
            }
            #pragma unroll
            for (int i = 0; i < 4; i++)
                #pragma unroll
                for (int j = 0; j < 2; j++)
                    mma_tf32(c[i][j], afr[i], bfr[j]);
            if (p.prec) {
                uint32_t afl[4][4], bfl[2][2];
                #pragma unroll
                for (int i = 0; i < 4; i++) {
                    int r = wm * 64 + i * 16 + (lane >> 2);
                    afl[i][0] = sAl[SIDX(r, krow)];
                    afl[i][1] = sAl[SIDX(r + 8, krow)];
                    afl[i][2] = sAl[SIDX(r, krow + 4)];
                    afl[i][3] = sAl[SIDX(r + 8, krow + 4)];
                }
                #pragma unroll
                for (int j = 0; j < 2; j++) {
                    int cc = wn * 16 + j * 8 + (lane >> 2);
                    bfl[j][0] = sWl[SIDX(cc, krow)];
                    bfl[j][1] = sWl[SIDX(cc, krow + 4)];
                }
                #pragma unroll
                for (int i = 0; i < 4; i++)
                    #pragma unroll
                    for (int j = 0; j < 2; j++) {
                        mma_tf32(c[i][j], afl[i], bfr[j]);
                        mma_tf32(c[i][j], afr[i], bfl[j]);
                    }
            }
        }
    }
    gemm_epilogue(c, bm, bn, bz, wm, wn, lane, p);
}

// =================== FP16 body (plain; double-buffered; m16n8k16) ===============
__device__ __forceinline__ void mma_body16(int bx, int by, int bz, const GP& p)
{
    int tid = threadIdx.x;
    int lane = tid & 31, wid = tid >> 5;
    int wm = wid & 1, wn = wid >> 1;
    int bn = bx * MM_BN;
    int bm = by * MM_BM;
    int kbase = bz * p.Kc;

    int a_m = tid >> 1, a_k = (tid & 1) * 8;
    int gm = bm + a_m;
    int arow = gm;
    if (p.rowmap) { int bb = gm / p.rowdiv; int pp = gm - bb * p.rowdiv; arow = p.rowmap[bb] * p.rowdiv + pp; }
    const float* aptr = p.A + (size_t)arow * p.lda + kbase + a_k;
    int w_k = tid >> 4, w_n = (tid & 15) * 4;
    const float* wptr = p.W + (size_t)(kbase + w_k) * p.ldw + bn + w_n;
    bool wok = (bn + w_n) < p.N;

    float c[4][2][4];
    #pragma unroll
    for (int i = 0; i < 4; i++)
        #pragma unroll
        for (int j = 0; j < 2; j++)
            #pragma unroll
            for (int q = 0; q < 4; q++) c[i][j][q] = 0.f;

    int iters = p.Kc / MM_BK;
    float4 pa0 = *(const float4*)(aptr);
    float4 pa1 = *(const float4*)(aptr + 4);
    float4 pw  = wok ? *(const float4*)(wptr) : make_float4(0,0,0,0);

    for (int it = 0; it < iters; it++) {
        uint32_t* stage = dynsh + (it & 1) * STAGE16_U32;
        uint32_t* sA16 = stage;                      // [128][12] u32 (8 half2 pairs + pad)
        uint32_t* sW16 = sA16 + MM_BM * SROW16;      // [64][12]

        {
            __half2 h[4];
            h[0] = __floats2half2_rn(pa0.x, pa0.y);
            h[1] = __floats2half2_rn(pa0.z, pa0.w);
            h[2] = __floats2half2_rn(pa1.x, pa1.y);
            h[3] = __floats2half2_rn(pa1.z, pa1.w);
            *(uint4*)&sA16[SIDX16(a_m, (a_k >> 1))] = *(uint4*)h;   // pair base 0 or 4
            __half wh[4] = {__float2half_rn(pw.x), __float2half_rn(pw.y),
                            __float2half_rn(pw.z), __float2half_rn(pw.w)};
            __half* wbase = (__half*)sW16;
            #pragma unroll
            for (int j = 0; j < 4; j++)
                wbase[(w_n + j) * (SROW16*2) + w_k] = wh[j];
        }
        __syncthreads();

        if (it + 1 < iters) {
            const float* an = aptr + (it + 1) * MM_BK;
            pa0 = *(const float4*)(an);
            pa1 = *(const float4*)(an + 4);
            pw  = wok ? *(const float4*)(wptr + (size_t)(it + 1) * MM_BK * p.ldw)
                      : make_float4(0,0,0,0);
        }

        int kp = lane & 3;   // pair index: k = kp*2; +4 → k+8
        uint32_t afr[4][4], bfr[2][2];
        #pragma unroll
        for (int i = 0; i < 4; i++) {
            int r = wm * 64 + i * 16 + (lane >> 2);
            afr[i][0] = sA16[SIDX16(r, kp)];
            afr[i][1] = sA16[SIDX16(r + 8, kp)];
            afr[i][2] = sA16[SIDX16(r, kp + 4)];
            afr[i][3] = sA16[SIDX16(r + 8, kp + 4)];
        }
        #pragma unroll
        for (int j = 0; j < 2; j++) {
            int cc = wn * 16 + j * 8 + (lane >> 2);
            bfr[j][0] = sW16[SIDX16(cc, kp)];
            bfr[j][1] = sW16[SIDX16(cc, kp + 4)];
        }
        #pragma unroll
        for (int i = 0; i < 4; i++)
            #pragma unroll
            for (int j = 0; j < 2; j++)
                mma_f16(c[i][j], afr[i], bfr[j]);
    }
    gemm_epilogue(c, bm, bn, bz, wm, wn, lane, p);
}

__global__ __launch_bounds__(256) void k_mma(GP p)
{
    mma_body(blockIdx.x, blockIdx.y, blockIdx.z, p);
}
__global__ __launch_bounds__(256) void k_mma16(GP p)
{
    mma_body16(blockIdx.x, blockIdx.y, blockIdx.z, p);
}
// combo: fp16 task a (preds) + tf32 task b (hgemm)
__global__ __launch_bounds__(256) void k_combo(GP a, GP b, int blocksA)
{
    int id = blockIdx.x;
    if (id < blocksA) {
        mma_body16(id % a.nbx, 0, id / a.nbx, a);
    } else {
        int i2 = id - blocksA;
        mma_body(i2 % b.nbx, 0, i2 / b.nbx, b);
    }
}

// ------------------- epilogue: init h / c (S=8, N=512) -------------------
__global__ void k_epi_hc(float* __restrict__ dst, const float* __restrict__ bias)
{
    int idx = blockIdx.x * 256 + threadIdx.x;
    int n = idx % D;
    float s = bias[n];
    #pragma unroll
    for (int z = 0; z < 8; z++) s += g_part[(size_t)z*B*D + idx];
    dst[idx] = s;
}

// ------------------- attention scores + softmax + emb slice of x -------------------
__global__ void k_escore(const float* __restrict__ w_full,
                         const float* __restrict__ b_full,
                         const float* __restrict__ b_dec,
                         const float* __restrict__ b_enc,
                         const float* __restrict__ emb_table,
                         const int* __restrict__ caps_in,
                         float* __restrict__ out, int t)
{
    int b = blockIdx.x;
    __shared__ float att2s[AA], ws[AA], es[P], red[256];
    int tid = threadIdx.x;
    for (int j = tid; j < AA; j += 256) {
        float s = b_dec[j] + b_enc[j];
        #pragma unroll
        for (int z = 0; z < HS; z++)
            s += g_part[(size_t)z*B*NCAT + (size_t)b*NCAT + j];
        att2s[j] = s;
        ws[j]    = w_full[j];
    }
    __syncthreads();
    int warp = tid >> 5, lane = tid & 31;
    float bf = *b_full;
    for (int p = warp; p < P; p += 8) {
        const float* row = g_att1 + ((size_t)b*P + p)*AA;
        float acc = 0.f;
        #pragma unroll 4
        for (int a = lane; a < AA; a += 32) {
            float v = row[a] + att2s[a];
            v = fmaxf(v, 0.f);
            acc += v * ws[a];
        }
        #pragma unroll
        for (int o = 16; o > 0; o >>= 1) acc += __shfl_down_sync(0xffffffffu, acc, o);
        if (lane == 0) es[p] = acc + bf;
    }
    __syncthreads();
    float m = -1e30f;
    for (int p = tid; p < P; p += 256) m = fmaxf(m, es[p]);
    red[tid] = m; __syncthreads();
    for (int s = 128; s > 0; s >>= 1) { if (tid < s) red[tid] = fmaxf(red[tid], red[tid+s]); __syncthreads(); }
    float mx = red[0]; __syncthreads();
    float sum = 0.f;
    for (int p = tid; p < P; p += 256) sum += expf(es[p] - mx);
    red[tid] = sum; __syncthreads();
    for (int s = 128; s > 0; s >>= 1) { if (tid < s) red[tid] += red[tid+s]; __syncthreads(); }
    float inv = 1.f / red[0];
    float maskv = (t < g_declen[b]) ? 1.f : 0.f;
    for (int p = tid; p < P; p += 256) {
        float al = expf(es[p] - mx) * inv;
        g_alpha[b*P + p] = al;
        out[OFF_ALPHAS + ((size_t)b*T + t)*P + p] = al * maskv;
    }
    int cap = caps_in[g_sort[b]*TCAP + t];
    if (tid < EMB/4) {
        const float4* esrc = (const float4*)(emb_table + (size_t)cap*EMB);
        float4* edst = (float4*)(g_x + (size_t)b*XDIM);
        edst[tid] = esrc[tid];
    }
}

// ------------------- awe (fp16 enc, 512 blocks); gate from hgemm partials -------
__global__ void k_awe(const float* __restrict__ b_fbeta)
{
    int b  = blockIdx.y;
    int e0 = blockIdx.x * 512;
    __shared__ float als[P];
    int tid = threadIdx.x;
    if (tid < P) als[tid] = g_alpha[b*P + tid];
    __syncthreads();
    int j0 = e0 + 2*tid;
    float acc0 = 0.f, acc1 = 0.f;
    const __half2* base = (const __half2*)(g_ench + (size_t)b*P*E + j0);
    #pragma unroll 2
    for (int p = 0; p < P; p++) {
        float2 v = __half22float2(base[(size_t)p*(E/2)]);
        float al = als[p];
        acc0 += v.x * al;
        acc1 += v.y * al;
    }
    float s0 = b_fbeta[j0], s1 = b_fbeta[j0 + 1];
    #pragma unroll
    for (int z = 0; z < HS; z++) {
        size_t o = (size_t)z*B*NCAT + (size_t)b*NCAT + AA + j0;
        s0 += g_part[o];
        s1 += g_part[o + 1];
    }
    float g0 = 1.f / (1.f + expf(-s0));
    float g1 = 1.f / (1.f + expf(-s1));
    float2* xd = (float2*)(g_x + (size_t)b*XDIM + EMB + LCD + j0);
    *xd = make_float2(g0 * acc0, g1 * acc1);
}

// ------------------- fused gates reduce (hh S=4 + x S=12) + LSTM -------------------
__global__ void k_lstm(const float* __restrict__ b_ih,
                       const float* __restrict__ b_hh, int t)
{
    int idx = blockIdx.x * 256 + threadIdx.x;
    int b = idx / D, j = idx % D;
    float gate4[4];
    #pragma unroll
    for (int g = 0; g < 4; g++) {
        int n = g * D + j;
        float s = b_ih[n] + b_hh[n];
        #pragma unroll
        for (int z = 0; z < HS; z++)
            s += g_part[(size_t)z*B*NCAT + (size_t)b*NCAT + AA + E + n];
        #pragma unroll
        for (int z = 0; z < XS; z++)
            s += g_part[XOFF + (size_t)z*B*G4 + (size_t)b*G4 + n];
        gate4[g] = s;
    }
    float si = 1.f / (1.f + expf(-gate4[0]));
    float sf = 1.f / (1.f + expf(-gate4[1]));
    float so = 1.f / (1.f + expf(-gate4[3]));
    float cn = sf * g_c[idx] + si * tanhf(gate4[2]);
    float hn = so * tanhf(cn);
    g_hnew[idx] = hn;
    if (t < g_declen[b]) { g_h[idx] = hn; g_c[idx] = cn; }
}

// ------------------- host launcher (single stream) -------------------
extern "C" void kernel_launch(void* const* d_in, const int* in_sizes, int n_in,
                              void* d_out, int out_size)
{
    const float* encoder_out  = (const float*)d_in[0];
    const int*   caps_in      = (const int*)  d_in[1];
    const int*   cap_len      = (const int*)  d_in[2];
    const int*   length_class = (const int*)  d_in[3];
    const float* W_enc_att    = (const float*)d_in[4];
    const float* b_enc_att    = (const float*)d_in[5];
    const float* W_dec_att    = (const float*)d_in[6];
    const float* b_dec_att    = (const float*)d_in[7];
    const float* w_full_att   = (const float*)d_in[8];
    const float* b_full_att   = (const float*)d_in[9];
    const float* W_init_h     = (const float*)d_in[10];
    const float* b_init_h     = (const float*)d_in[11];
    const float* W_init_c     = (const float*)d_in[12];
    const float* b_init_c     = (const float*)d_in[13];
    const float* W_fbeta      = (const float*)d_in[14];
    const float* b_fbeta      = (const float*)d_in[15];
    const float* emb_table    = (const float*)d_in[16];
    const float* lc_table     = (const float*)d_in[17];
    const float* W_fc         = (const float*)d_in[18];
    const float* b_fc         = (const float*)d_in[19];
    const float* W_ih         = (const float*)d_in[20];
    const float* b_ih         = (const float*)d_in[21];
    const float* W_hh         = (const float*)d_in[22];
    const float* b_hh         = (const float*)d_in[23];
    float* out = (float*)d_out;

    void* tmp;
    float *p_att1, *p_mean, *p_h, *p_c, *p_hnew, *p_x, *p_Wcat, *p_part;
    int *p_sort, *p_declen;
    cudaGetSymbolAddress(&tmp, g_att1);   p_att1  = (float*)tmp;
    cudaGetSymbolAddress(&tmp, g_mean);   p_mean  = (float*)tmp;
    cudaGetSymbolAddress(&tmp, g_h);      p_h     = (float*)tmp;
    cudaGetSymbolAddress(&tmp, g_c);      p_c     = (float*)tmp;
    cudaGetSymbolAddress(&tmp, g_hnew);   p_hnew  = (float*)tmp;
    cudaGetSymbolAddress(&tmp, g_x);      p_x     = (float*)tmp;
    cudaGetSymbolAddress(&tmp, g_Wcat);   p_Wcat  = (float*)tmp;
    cudaGetSymbolAddress(&tmp, g_part);   p_part  = (float*)tmp;
    cudaGetSymbolAddress(&tmp, g_sort);   p_sort  = (int*)tmp;
    cudaGetSymbolAddress(&tmp, g_declen); p_declen= (int*)tmp;

    // opt-in to large dynamic smem (host attribute; no device alloc)
    cudaFuncSetAttribute(k_mma,   cudaFuncAttributeMaxDynamicSharedMemorySize, DSMEM_BYTES);
    cudaFuncSetAttribute(k_mma16, cudaFuncAttributeMaxDynamicSharedMemorySize, DSMEM_BYTES);
    cudaFuncSetAttribute(k_combo, cudaFuncAttributeMaxDynamicSharedMemorySize, DSMEM_BYTES);

    const int PRED_BLOCKS = (V + MM_BN - 1) / MM_BN;   // 157
    const int HG_BLOCKS   = (NCAT / MM_BN) * HS;       // 288

    // ---- setup ----
    k_sort<<<1, B>>>(caps_in, cap_len, length_class, lc_table, out);
    k_concatW<<<(D*NCAT + 255)/256, 256>>>(W_dec_att, W_fbeta, W_hh);
    k_prep<<<dim3(E/256, B), 256>>>(encoder_out);

    // h0 / c0 : precise TF32, S=8 (base partial region)
    GP h0 = {p_mean, E, W_init_h, D, p_part, D, B, D, 256,
             nullptr, 0, nullptr, nullptr, 0, 1, D/MM_BN};
    k_mma<<<dim3(D/MM_BN, 1, 8), 256, DSMEM_BYTES>>>(h0);
    k_epi_hc<<<(B*D)/256, 256>>>(p_h, b_init_h);
    GP c0 = h0; c0.W = W_init_c;
    k_mma<<<dim3(D/MM_BN, 1, 8), 256, DSMEM_BYTES>>>(c0);
    k_epi_hc<<<(B*D)/256, 256>>>(p_c, b_init_c);

    // att1 = enc[sort] @ W_enc_att — fp16 tensor cores (same 10-bit mantissa as TF32)
    GP a1 = {encoder_out, E, W_enc_att, AA, p_att1, AA, B*P, AA, E,
             p_sort, P, nullptr, nullptr, 0, 0, AA/MM_BN};
    k_mma16<<<dim3(AA/MM_BN, (B*P)/MM_BM, 1), 256, DSMEM16_BYTES>>>(a1);

    GP hg = {p_h, D, p_Wcat, NCAT, p_part, NCAT, B, NCAT, 512/HS,
             nullptr, 0, nullptr, nullptr, 0, 1, NCAT/MM_BN};
    GP ih = {p_x, XDIM, W_ih, G4, p_part + XOFF, G4, B, G4, XDIM/XS,
             nullptr, 0, nullptr, nullptr, 0, 1, G4/MM_BN};

    for (int t = 0; t < T; t++) {
        if (t == 0) {
            k_mma<<<dim3(NCAT/MM_BN, 1, HS), 256, DSMEM_BYTES>>>(hg);
        } else {
            // combo: preds(t-1) fp16 [fused bias+mask, direct out] + hgemm(t) precise TF32
            GP pr = {p_hnew, D, W_fc, V, out + (size_t)(t-1)*V, T*V, B, V, D,
                     nullptr, 0, b_fc, p_declen, t-1, 0, PRED_BLOCKS};
            k_combo<<<PRED_BLOCKS + HG_BLOCKS, 256, DSMEM_BYTES>>>(pr, hg, PRED_BLOCKS);
        }
        // scores + softmax + alphas out + emb slice
        k_escore<<<B, 256>>>(w_full_att, b_full_att, b_dec_att, b_enc_att,
                             emb_table, caps_in, out, t);
        // awe fp16, gate sigmoid inline, writes gate*awe into x
        k_awe<<<dim3(E/512, B), 256>>>(b_fbeta);
        // x @ W_ih — precise TF32, S=12
        k_mma<<<dim3(G4/MM_BN, 1, XS), 256, DSMEM_BYTES>>>(ih);
        // gates reduce + LSTM cell + masked carry
        k_lstm<<<(B*D)/256, 256>>>(b_ih, b_hh, t);
    }
    // final preds(T-1) — fp16
    GP prF = {p_hnew, D, W_fc, V, out + (size_t)(T-1)*V, T*V, B, V, D,
              nullptr, 0, b_fc, p_declen, T-1, 0, PRED_BLOCKS};
    k_mma16<<<dim3(PRED_BLOCKS, 1, 1), 256, DSMEM16_BYTES>>>(prF);
}

// round 17
// speedup vs baseline: 1.0645x; 1.0645x over previous
#include <cuda_runtime.h>
#include <cuda_fp16.h>
#include <math.h>
#include <stdint.h>

// Problem constants
#define B   128
#define P   196
#define E   2048
#define AA  512
#define EMB 512
#define D   512
#define V   10000
#define LCD 128
#define TCAP 26
#define T   25
#define XE  (EMB + LCD)        // 640 : [emb | style]
#define G4  (4*D)              // 2048
#define NCAT (AA + E + G4)     // 4608
#define KX  E                  // per-step W_ih K (gate*awe part) = 2048

// partial-buffer layout: hgemm S=4 over NCAT at base; W_ih S=8 at XOFF
#define HS   4
#define XS   8
#define XOFF ((size_t)HS*B*NCAT)
#define PART_TOTAL (XOFF + (size_t)XS*B*G4)

// Output layout: predictions (B,T,V), caps (B,TCAP), dec_len (B,), alphas (B,T,P), sort_ind (B,)
#define OFF_PRED   ((size_t)0)
#define OFF_CAPS   ((size_t)B*T*V)
#define OFF_DECLEN (OFF_CAPS + (size_t)B*TCAP)
#define OFF_ALPHAS (OFF_DECLEN + (size_t)B)
#define OFF_SORT   (OFF_ALPHAS + (size_t)B*T*P)

// ------------------- scratch -------------------
__device__ float  g_att1[(size_t)B*P*AA];
__device__ __half g_ench[(size_t)B*P*E];
__device__ float  g_Wcat[(size_t)D*NCAT];
__device__ float  g_part[PART_TOTAL];
__device__ float  g_xe[(size_t)T*B*XE];      // [t*B+b][640] emb|style
__device__ float  g_embih[(size_t)T*B*G4];   // (xe @ W_ih[0:640]) + b_ih
__device__ float  g_mean[B*E];
__device__ float  g_h[B*D];
__device__ float  g_c[B*D];
__device__ float  g_hnew[B*D];
__device__ float  g_alpha[B*P];
__device__ float  g_x[B*KX];                 // gate*awe only
__device__ int    g_sort[B];
__device__ int    g_declen[B];

// ------------------- sort + small outputs -------------------
__global__ void k_sort(const int* __restrict__ caps_in,
                       const int* __restrict__ cap_len,
                       float* __restrict__ out)
{
    __shared__ int cls[B];
    int i = threadIdx.x;
    cls[i] = cap_len[i];
    __syncthreads();
    int my = cls[i];
    int rank = 0;
    for (int j = 0; j < B; j++) {
        int cj = cls[j];
        if (cj > my || (cj == my && j < i)) rank++;
    }
    g_sort[rank] = i;
    __syncthreads();
    int si = g_sort[i];
    int dl = cls[si] - 1;
    g_declen[i] = dl;
    out[OFF_DECLEN + i] = (float)dl;
    out[OFF_SORT + i]   = (float)si;
    for (int tt = 0; tt < TCAP; tt++)
        out[OFF_CAPS + (size_t)i*TCAP + tt] = (float)caps_in[si*TCAP + tt];
}

// ------------------- build xe = [emb_t | style] for all t -------------------
__global__ void k_buildxe(const int* __restrict__ caps_in,
                          const float* __restrict__ emb_table,
                          const int* __restrict__ length_class,
                          const float* __restrict__ lc_table)
{
    int tb = blockIdx.x;          // 0..T*B-1
    int t = tb / B, b = tb % B;
    int col = threadIdx.x;        // 640
    int si = g_sort[b];
    float v;
    if (col < EMB) {
        int cap = caps_in[si*TCAP + t];
        v = emb_table[(size_t)cap*EMB + col];
    } else {
        v = lc_table[length_class[si]*LCD + (col - EMB)];
    }
    g_xe[(size_t)tb*XE + col] = v;
}

// ------------------- fused: mean over pixels + sorted fp16 copy -------------------
__global__ void k_prep(const float* __restrict__ enc)
{
    int b = blockIdx.y;
    int e = blockIdx.x * 256 + threadIdx.x;
    const float* base = enc + (size_t)g_sort[b]*P*E + e;
    __half* hbase = g_ench + (size_t)b*P*E + e;
    float s = 0.f;
    #pragma unroll 4
    for (int p = 0; p < P; p++) {
        float v = base[(size_t)p*E];
        s += v;
        hbase[(size_t)p*E] = __float2half_rn(v);
    }
    g_mean[b*E + e] = s * (1.0f / (float)P);
}

// ------------------- concat weights -------------------
__global__ void k_concatW(const float* __restrict__ Wdec,
                          const float* __restrict__ Wfb,
                          const float* __restrict__ Whh)
{
    int idx = blockIdx.x * 256 + threadIdx.x;
    if (idx >= D * NCAT) return;
    int k = idx / NCAT, n = idx % NCAT;
    float v;
    if (n < AA)            v = Wdec[k*AA + n];
    else if (n < AA + E)   v = Wfb[k*E + (n - AA)];
    else                   v = Whh[k*G4 + (n - AA - E)];
    g_Wcat[idx] = v;
}

// =================== common GEMM defs ===================
#define MM_BM 128
#define MM_BN 64
#define MM_BK 16

// fp16 stage: [row][8 half2 pairs], padded row = 12 u32 (48B, 16B-aligned)
#define SROW16 12
#define SIDX16(r,kp) ((r)*SROW16 + (kp))
#define STAGE16_U32 ((MM_BM + MM_BN) * SROW16)    // 2304 u32 (plain: hi only)
#define STAGE16P_U32 (2 * STAGE16_U32)            // 4608 u32 (precise: hi + lo)
#define DSMEM16_BYTES  (2 * STAGE16_U32 * 4)      // 18432
#define DSMEM16P_BYTES (2 * STAGE16P_U32 * 4)     // 36864

struct GP {
    const float* A; int lda;
    const float* W; int ldw;
    float* C; int ldc;
    int M, N, Kc;
    const int* rowmap; int rowdiv;
    const float* bias;
    const int* declen; int tstep;
    int prec;
    int nbx;   // x-blocks for 1D decomposition in combo
};

__device__ __forceinline__ void mma_f16(float* c, const uint32_t* a, const uint32_t* b) {
    asm volatile("mma.sync.aligned.m16n8k16.row.col.f32.f16.f16.f32 "
                 "{%0,%1,%2,%3}, {%4,%5,%6,%7}, {%8,%9}, {%0,%1,%2,%3};"
                 : "+f"(c[0]), "+f"(c[1]), "+f"(c[2]), "+f"(c[3])
                 : "r"(a[0]), "r"(a[1]), "r"(a[2]), "r"(a[3]),
                   "r"(b[0]), "r"(b[1]));
}

extern __shared__ uint32_t dynsh[];

// ---------- shared epilogue ----------
__device__ __forceinline__ void gemm_epilogue(float c[4][2][4], int bm, int bn, int bz,
                                              int wm, int wn, int lane, const GP& p)
{
    if (p.bias) {
        #pragma unroll
        for (int i = 0; i < 4; i++) {
            int r0 = bm + wm * 64 + i * 16 + (lane >> 2);
            float rs0 = p.declen ? ((p.tstep < p.declen[r0])     ? 1.f : 0.f) : 1.f;
            float rs8 = p.declen ? ((p.tstep < p.declen[r0 + 8]) ? 1.f : 0.f) : 1.f;
            #pragma unroll
            for (int j = 0; j < 2; j++) {
                int cc = bn + wn * 16 + j * 8 + (lane & 3) * 2;
                if (cc < p.N) {
                    float b0 = p.bias[cc], b1 = p.bias[cc + 1];
                    *(float2*)&p.C[(size_t)r0 * p.ldc + cc] =
                        make_float2((c[i][j][0] + b0) * rs0, (c[i][j][1] + b1) * rs0);
                    *(float2*)&p.C[(size_t)(r0+8) * p.ldc + cc] =
                        make_float2((c[i][j][2] + b0) * rs8, (c[i][j][3] + b1) * rs8);
                }
            }
        }
    } else {
        float* pout = p.C + (size_t)bz * p.M * p.N;
        #pragma unroll
        for (int i = 0; i < 4; i++) {
            int r0 = bm + wm * 64 + i * 16 + (lane >> 2);
            #pragma unroll
            for (int j = 0; j < 2; j++) {
                int cc = bn + wn * 16 + j * 8 + (lane & 3) * 2;
                if (cc < p.N) {
                    *(float2*)&pout[(size_t)r0 * p.ldc + cc]     = make_float2(c[i][j][0], c[i][j][1]);
                    *(float2*)&pout[(size_t)(r0+8) * p.ldc + cc] = make_float2(c[i][j][2], c[i][j][3]);
                }
            }
        }
    }
}

// =================== FP16 plain body (m16n8k16, double-buffered) ===============
__device__ __forceinline__ void mma_body16(int bx, int by, int bz, const GP& p)
{
    int tid = threadIdx.x;
    int lane = tid & 31, wid = tid >> 5;
    int wm = wid & 1, wn = wid >> 1;
    int bn = bx * MM_BN;
    int bm = by * MM_BM;
    int kbase = bz * p.Kc;

    int a_m = tid >> 1, a_k = (tid & 1) * 8;
    int gm = bm + a_m;
    int arow = gm;
    if (p.rowmap) { int bb = gm / p.rowdiv; int pp = gm - bb * p.rowdiv; arow = p.rowmap[bb] * p.rowdiv + pp; }
    const float* aptr = p.A + (size_t)arow * p.lda + kbase + a_k;
    int w_k = tid >> 4, w_n = (tid & 15) * 4;
    const float* wptr = p.W + (size_t)(kbase + w_k) * p.ldw + bn + w_n;
    bool wok = (bn + w_n) < p.N;

    float c[4][2][4];
    #pragma unroll
    for (int i = 0; i < 4; i++)
        #pragma unroll
        for (int j = 0; j < 2; j++)
            #pragma unroll
            for (int q = 0; q < 4; q++) c[i][j][q] = 0.f;

    int iters = p.Kc / MM_BK;
    float4 pa0 = *(const float4*)(aptr);
    float4 pa1 = *(const float4*)(aptr + 4);
    float4 pw  = wok ? *(const float4*)(wptr) : make_float4(0,0,0,0);

    for (int it = 0; it < iters; it++) {
        uint32_t* stage = dynsh + (it & 1) * STAGE16_U32;
        uint32_t* sA16 = stage;
        uint32_t* sW16 = sA16 + MM_BM * SROW16;

        {
            __half2 h[4];
            h[0] = __floats2half2_rn(pa0.x, pa0.y);
            h[1] = __floats2half2_rn(pa0.z, pa0.w);
            h[2] = __floats2half2_rn(pa1.x, pa1.y);
            h[3] = __floats2half2_rn(pa1.z, pa1.w);
            *(uint4*)&sA16[SIDX16(a_m, (a_k >> 1))] = *(uint4*)h;
            __half wh[4] = {__float2half_rn(pw.x), __float2half_rn(pw.y),
                            __float2half_rn(pw.z), __float2half_rn(pw.w)};
            __half* wbase = (__half*)sW16;
            #pragma unroll
            for (int j = 0; j < 4; j++)
                wbase[(w_n + j) * (SROW16*2) + w_k] = wh[j];
        }
        __syncthreads();

        if (it + 1 < iters) {
            const float* an = aptr + (it + 1) * MM_BK;
            pa0 = *(const float4*)(an);
            pa1 = *(const float4*)(an + 4);
            pw  = wok ? *(const float4*)(wptr + (size_t)(it + 1) * MM_BK * p.ldw)
                      : make_float4(0,0,0,0);
        }

        int kp = lane & 3;
        uint32_t afr[4][4], bfr[2][2];
        #pragma unroll
        for (int i = 0; i < 4; i++) {
            int r = wm * 64 + i * 16 + (lane >> 2);
            afr[i][0] = sA16[SIDX16(r, kp)];
            afr[i][1] = sA16[SIDX16(r + 8, kp)];
            afr[i][2] = sA16[SIDX16(r, kp + 4)];
            afr[i][3] = sA16[SIDX16(r + 8, kp + 4)];
        }
        #pragma unroll
        for (int j = 0; j < 2; j++) {
            int cc = wn * 16 + j * 8 + (lane >> 2);
            bfr[j][0] = sW16[SIDX16(cc, kp)];
            bfr[j][1] = sW16[SIDX16(cc, kp + 4)];
        }
        #pragma unroll
        for (int i = 0; i < 4; i++)
            #pragma unroll
            for (int j = 0; j < 2; j++)
                mma_f16(c[i][j], afr[i], bfr[j]);
    }
    gemm_epilogue(c, bm, bn, bz, wm, wn, lane, p);
}

// =================== FP16 PRECISE body (2-term hi/lo split; ~fp32 accuracy) ========
// hi = fp16(x), lo = fp16(x - hi); omitted lo*lo term is O(2^-22).
__device__ __forceinline__ void mma_body16p(int bx, int by, int bz, const GP& p)
{
    int tid = threadIdx.x;
    int lane = tid & 31, wid = tid >> 5;
    int wm = wid & 1, wn = wid >> 1;
    int bn = bx * MM_BN;
    int bm = by * MM_BM;
    int kbase = bz * p.Kc;

    int a_m = tid >> 1, a_k = (tid & 1) * 8;
    int gm = bm + a_m;
    int arow = gm;
    if (p.rowmap) { int bb = gm / p.rowdiv; int pp = gm - bb * p.rowdiv; arow = p.rowmap[bb] * p.rowdiv + pp; }
    const float* aptr = p.A + (size_t)arow * p.lda + kbase + a_k;
    int w_k = tid >> 4, w_n = (tid & 15) * 4;
    const float* wptr = p.W + (size_t)(kbase + w_k) * p.ldw + bn + w_n;
    bool wok = (bn + w_n) < p.N;

    float c[4][2][4];
    #pragma unroll
    for (int i = 0; i < 4; i++)
        #pragma unroll
        for (int j = 0; j < 2; j++)
            #pragma unroll
            for (int q = 0; q < 4; q++) c[i][j][q] = 0.f;

    int iters = p.Kc / MM_BK;
    float4 pa0 = *(const float4*)(aptr);
    float4 pa1 = *(const float4*)(aptr + 4);
    float4 pw  = wok ? *(const float4*)(wptr) : make_float4(0,0,0,0);

    for (int it = 0; it < iters; it++) {
        uint32_t* stage = dynsh + (it & 1) * STAGE16P_U32;
        uint32_t* sAh = stage;
        uint32_t* sWh = sAh + MM_BM * SROW16;
        uint32_t* sAl = sWh + MM_BN * SROW16;
        uint32_t* sWl = sAl + MM_BM * SROW16;

        {
            float av[8] = {pa0.x,pa0.y,pa0.z,pa0.w,pa1.x,pa1.y,pa1.z,pa1.w};
            __half hh[8], hl[8];
            #pragma unroll
            for (int q = 0; q < 8; q++) {
                hh[q] = __float2half_rn(av[q]);
                hl[q] = __float2half_rn(av[q] - __half2float(hh[q]));
            }
            *(uint4*)&sAh[SIDX16(a_m, (a_k >> 1))] = *(uint4*)hh;
            *(uint4*)&sAl[SIDX16(a_m, (a_k >> 1))] = *(uint4*)hl;

            float wv[4] = {pw.x, pw.y, pw.z, pw.w};
            __half* whb = (__half*)sWh;
            __half* wlb = (__half*)sWl;
            #pragma unroll
            for (int j = 0; j < 4; j++) {
                __half h = __float2half_rn(wv[j]);
                __half l = __float2half_rn(wv[j] - __half2float(h));
                whb[(w_n + j) * (SROW16*2) + w_k] = h;
                wlb[(w_n + j) * (SROW16*2) + w_k] = l;
            }
        }
        __syncthreads();

        if (it + 1 < iters) {
            const float* an = aptr + (it + 1) * MM_BK;
            pa0 = *(const float4*)(an);
            pa1 = *(const float4*)(an + 4);
            pw  = wok ? *(const float4*)(wptr + (size_t)(it + 1) * MM_BK * p.ldw)
                      : make_float4(0,0,0,0);
        }

        int kp = lane & 3;
        uint32_t afh[4][4], afl[4][4], bfh[2][2], bfl[2][2];
        #pragma unroll
        for (int i = 0; i < 4; i++) {
            int r = wm * 64 + i * 16 + (lane >> 2);
            afh[i][0] = sAh[SIDX16(r, kp)];
            afh[i][1] = sAh[SIDX16(r + 8, kp)];
            afh[i][2] = sAh[SIDX16(r, kp + 4)];
            afh[i][3] = sAh[SIDX16(r + 8, kp + 4)];
            afl[i][0] = sAl[SIDX16(r, kp)];
            afl[i][1] = sAl[SIDX16(r + 8, kp)];
            afl[i][2] = sAl[SIDX16(r, kp + 4)];
            afl[i][3] = sAl[SIDX16(r + 8, kp + 4)];
        }
        #pragma unroll
        for (int j = 0; j < 2; j++) {
            int cc = wn * 16 + j * 8 + (lane >> 2);
            bfh[j][0] = sWh[SIDX16(cc, kp)];
            bfh[j][1] = sWh[SIDX16(cc, kp + 4)];
            bfl[j][0] = sWl[SIDX16(cc, kp)];
            bfl[j][1] = sWl[SIDX16(cc, kp + 4)];
        }
        #pragma unroll
        for (int i = 0; i < 4; i++)
            #pragma unroll
            for (int j = 0; j < 2; j++) {
                mma_f16(c[i][j], afh[i], bfh[j]);
                mma_f16(c[i][j], afh[i], bfl[j]);
                mma_f16(c[i][j], afl[i], bfh[j]);
            }
    }
    gemm_epilogue(c, bm, bn, bz, wm, wn, lane, p);
}

__global__ __launch_bounds__(256) void k_mma16(GP p)
{
    mma_body16(blockIdx.x, blockIdx.y, blockIdx.z, p);
}
__global__ __launch_bounds__(256) void k_mma16p(GP p)
{
    mma_body16p(blockIdx.x, blockIdx.y, blockIdx.z, p);
}
// combo: plain fp16 task a (preds) + precise fp16 task b (hgemm)
__global__ __launch_bounds__(256) void k_combo(GP a, GP b, int blocksA)
{
    int id = blockIdx.x;
    if (id < blocksA) {
        mma_body16(id % a.nbx, 0, id / a.nbx, a);
    } else {
        int i2 = id - blocksA;
        mma_body16p(i2 % b.nbx, 0, i2 / b.nbx, b);
    }
}

// ------------------- epilogue: init h / c (S=8, N=512) -------------------
__global__ void k_epi_hc(float* __restrict__ dst, const float* __restrict__ bias)
{
    int idx = blockIdx.x * 256 + threadIdx.x;
    int n = idx % D;
    float s = bias[n];
    #pragma unroll
    for (int z = 0; z < 8; z++) s += g_part[(size_t)z*B*D + idx];
    dst[idx] = s;
}

// ------------------- attention scores + softmax -------------------
__global__ void k_escore(const float* __restrict__ w_full,
                         const float* __restrict__ b_full,
                         const float* __restrict__ b_dec,
                         const float* __restrict__ b_enc,
                         float* __restrict__ out, int t)
{
    int b = blockIdx.x;
    __shared__ float att2s[AA], ws[AA], es[P], red[256];
    int tid = threadIdx.x;
    for (int j = tid; j < AA; j += 256) {
        float s = b_dec[j] + b_enc[j];
        #pragma unroll
        for (int z = 0; z < HS; z++)
            s += g_part[(size_t)z*B*NCAT + (size_t)b*NCAT + j];
        att2s[j] = s;
        ws[j]    = w_full[j];
    }
    __syncthreads();
    int warp = tid >> 5, lane = tid & 31;
    float bf = *b_full;
    for (int p = warp; p < P; p += 8) {
        const float* row = g_att1 + ((size_t)b*P + p)*AA;
        float acc = 0.f;
        #pragma unroll 4
        for (int a = lane; a < AA; a += 32) {
            float v = row[a] + att2s[a];
            v = fmaxf(v, 0.f);
            acc += v * ws[a];
        }
        #pragma unroll
        for (int o = 16; o > 0; o >>= 1) acc += __shfl_down_sync(0xffffffffu, acc, o);
        if (lane == 0) es[p] = acc + bf;
    }
    __syncthreads();
    float m = -1e30f;
    for (int p = tid; p < P; p += 256) m = fmaxf(m, es[p]);
    red[tid] = m; __syncthreads();
    for (int s = 128; s > 0; s >>= 1) { if (tid < s) red[tid] = fmaxf(red[tid], red[tid+s]); __syncthreads(); }
    float mx = red[0]; __syncthreads();
    float sum = 0.f;
    for (int p = tid; p < P; p += 256) sum += expf(es[p] - mx);
    red[tid] = sum; __syncthreads();
    for (int s = 128; s > 0; s >>= 1) { if (tid < s) red[tid] += red[tid+s]; __syncthreads(); }
    float inv = 1.f / red[0];
    float maskv = (t < g_declen[b]) ? 1.f : 0.f;
    for (int p = tid; p < P; p += 256) {
        float al = expf(es[p] - mx) * inv;
        g_alpha[b*P + p] = al;
        out[OFF_ALPHAS + ((size_t)b*T + t)*P + p] = al * maskv;
    }
}

// ------------------- awe (fp16 enc, 512 blocks); gate from hgemm partials -------
__global__ void k_awe(const float* __restrict__ b_fbeta)
{
    int b  = blockIdx.y;
    int e0 = blockIdx.x * 512;
    __shared__ float als[P];
    int tid = threadIdx.x;
    if (tid < P) als[tid] = g_alpha[b*P + tid];
    __syncthreads();
    int j0 = e0 + 2*tid;
    float acc0 = 0.f, acc1 = 0.f;
    const __half2* base = (const __half2*)(g_ench + (size_t)b*P*E + j0);
    #pragma unroll 2
    for (int p = 0; p < P; p++) {
        float2 v = __half22float2(base[(size_t)p*(E/2)]);
        float al = als[p];
        acc0 += v.x * al;
        acc1 += v.y * al;
    }
    float s0 = b_fbeta[j0], s1 = b_fbeta[j0 + 1];
    #pragma unroll
    for (int z = 0; z < HS; z++) {
        size_t o = (size_t)z*B*NCAT + (size_t)b*NCAT + AA + j0;
        s0 += g_part[o];
        s1 += g_part[o + 1];
    }
    float g0 = 1.f / (1.f + expf(-s0));
    float g1 = 1.f / (1.f + expf(-s1));
    float2* xd = (float2*)(g_x + (size_t)b*KX + j0);
    *xd = make_float2(g0 * acc0, g1 * acc1);
}

// ------------------- fused gates reduce (embih + hh S=4 + x S=8) + LSTM -----------
__global__ void k_lstm(const float* __restrict__ b_hh, int t)
{
    int idx = blockIdx.x * 256 + threadIdx.x;
    int b = idx / D, j = idx % D;
    const float* embih = g_embih + (size_t)(t*B + b)*G4;
    float gate4[4];
    #pragma unroll
    for (int g = 0; g < 4; g++) {
        int n = g * D + j;
        float s = b_hh[n] + embih[n];   // embih already includes b_ih
        #pragma unroll
        for (int z = 0; z < HS; z++)
            s += g_part[(size_t)z*B*NCAT + (size_t)b*NCAT + AA + E + n];
        #pragma unroll
        for (int z = 0; z < XS; z++)
            s += g_part[XOFF + (size_t)z*B*G4 + (size_t)b*G4 + n];
        gate4[g] = s;
    }
    float si = 1.f / (1.f + expf(-gate4[0]));
    float sf = 1.f / (1.f + expf(-gate4[1]));
    float so = 1.f / (1.f + expf(-gate4[3]));
    float cn = sf * g_c[idx] + si * tanhf(gate4[2]);
    float hn = so * tanhf(cn);
    g_hnew[idx] = hn;
    if (t < g_declen[b]) { g_h[idx] = hn; g_c[idx] = cn; }
}

// ------------------- host launcher (single stream) -------------------
extern "C" void kernel_launch(void* const* d_in, const int* in_sizes, int n_in,
                              void* d_out, int out_size)
{
    const float* encoder_out  = (const float*)d_in[0];
    const int*   caps_in      = (const int*)  d_in[1];
    const int*   cap_len      = (const int*)  d_in[2];
    const int*   length_class = (const int*)  d_in[3];
    const float* W_enc_att    = (const float*)d_in[4];
    const float* b_enc_att    = (const float*)d_in[5];
    const float* W_dec_att    = (const float*)d_in[6];
    const float* b_dec_att    = (const float*)d_in[7];
    const float* w_full_att   = (const float*)d_in[8];
    const float* b_full_att   = (const float*)d_in[9];
    const float* W_init_h     = (const float*)d_in[10];
    const float* b_init_h     = (const float*)d_in[11];
    const float* W_init_c     = (const float*)d_in[12];
    const float* b_init_c     = (const float*)d_in[13];
    const float* W_fbeta      = (const float*)d_in[14];
    const float* b_fbeta      = (const float*)d_in[15];
    const float* emb_table    = (const float*)d_in[16];
    const float* lc_table     = (const float*)d_in[17];
    const float* W_fc         = (const float*)d_in[18];
    const float* b_fc         = (const float*)d_in[19];
    const float* W_ih         = (const float*)d_in[20];
    const float* b_ih         = (const float*)d_in[21];
    const float* W_hh         = (const float*)d_in[22];
    const float* b_hh         = (const float*)d_in[23];
    float* out = (float*)d_out;

    void* tmp;
    float *p_att1, *p_mean, *p_h, *p_c, *p_hnew, *p_x, *p_Wcat, *p_part, *p_xe, *p_embih;
    int *p_sort, *p_declen;
    cudaGetSymbolAddress(&tmp, g_att1);   p_att1  = (float*)tmp;
    cudaGetSymbolAddress(&tmp, g_mean);   p_mean  = (float*)tmp;
    cudaGetSymbolAddress(&tmp, g_h);      p_h     = (float*)tmp;
    cudaGetSymbolAddress(&tmp, g_c);      p_c     = (float*)tmp;
    cudaGetSymbolAddress(&tmp, g_hnew);   p_hnew  = (float*)tmp;
    cudaGetSymbolAddress(&tmp, g_x);      p_x     = (float*)tmp;
    cudaGetSymbolAddress(&tmp, g_Wcat);   p_Wcat  = (float*)tmp;
    cudaGetSymbolAddress(&tmp, g_part);   p_part  = (float*)tmp;
    cudaGetSymbolAddress(&tmp, g_xe);     p_xe    = (float*)tmp;
    cudaGetSymbolAddress(&tmp, g_embih);  p_embih = (float*)tmp;
    cudaGetSymbolAddress(&tmp, g_sort);   p_sort  = (int*)tmp;
    cudaGetSymbolAddress(&tmp, g_declen); p_declen= (int*)tmp;

    cudaFuncSetAttribute(k_mma16,  cudaFuncAttributeMaxDynamicSharedMemorySize, DSMEM16P_BYTES);
    cudaFuncSetAttribute(k_mma16p, cudaFuncAttributeMaxDynamicSharedMemorySize, DSMEM16P_BYTES);
    cudaFuncSetAttribute(k_combo,  cudaFuncAttributeMaxDynamicSharedMemorySize, DSMEM16P_BYTES);

    const int PRED_BLOCKS = (V + MM_BN - 1) / MM_BN;   // 157
    const int HG_BLOCKS   = (NCAT / MM_BN) * HS;       // 288

    // ---- setup ----
    k_sort<<<1, B>>>(caps_in, cap_len, out);
    k_concatW<<<(D*NCAT + 255)/256, 256>>>(W_dec_att, W_fbeta, W_hh);
    k_buildxe<<<T*B, XE>>>(caps_in, emb_table, length_class, lc_table);
    k_prep<<<dim3(E/256, B), 256>>>(encoder_out);

    // embih = xe @ W_ih[0:640] + b_ih  (precise fp16; M=3200=25*128, direct write)
    GP ei = {p_xe, XE, W_ih, G4, p_embih, G4, T*B, G4, XE,
             nullptr, 0, b_ih, nullptr, 0, 1, G4/MM_BN};
    k_mma16p<<<dim3(G4/MM_BN, (T*B)/MM_BM, 1), 256, DSMEM16P_BYTES>>>(ei);

    // h0 / c0 : precise fp16, S=8 (base partial region)
    GP h0 = {p_mean, E, W_init_h, D, p_part, D, B, D, 256,
             nullptr, 0, nullptr, nullptr, 0, 1, D/MM_BN};
    k_mma16p<<<dim3(D/MM_BN, 1, 8), 256, DSMEM16P_BYTES>>>(h0);
    k_epi_hc<<<(B*D)/256, 256>>>(p_h, b_init_h);
    GP c0 = h0; c0.W = W_init_c;
    k_mma16p<<<dim3(D/MM_BN, 1, 8), 256, DSMEM16P_BYTES>>>(c0);
    k_epi_hc<<<(B*D)/256, 256>>>(p_c, b_init_c);

    // att1 = enc[sort] @ W_enc_att — plain fp16, row-remapped A
    GP a1 = {encoder_out, E, W_enc_att, AA, p_att1, AA, B*P, AA, E,
             p_sort, P, nullptr, nullptr, 0, 0, AA/MM_BN};
    k_mma16<<<dim3(AA/MM_BN, (B*P)/MM_BM, 1), 256, DSMEM16_BYTES>>>(a1);

    GP hg = {p_h, D, p_Wcat, NCAT, p_part, NCAT, B, NCAT, 512/HS,
             nullptr, 0, nullptr, nullptr, 0, 1, NCAT/MM_BN};
    GP ih = {p_x, KX, W_ih + (size_t)XE*G4, G4, p_part + XOFF, G4, B, G4, KX/XS,
             nullptr, 0, nullptr, nullptr, 0, 1, G4/MM_BN};

    for (int t = 0; t < T; t++) {
        if (t == 0) {
            k_mma16p<<<dim3(NCAT/MM_BN, 1, HS), 256, DSMEM16P_BYTES>>>(hg);
        } else {
            // combo: preds(t-1) plain fp16 [bias+mask, direct out] + hgemm(t) precise fp16
            GP pr = {p_hnew, D, W_fc, V, out + (size_t)(t-1)*V, T*V, B, V, D,
                     nullptr, 0, b_fc, p_declen, t-1, 0, PRED_BLOCKS};
            k_combo<<<PRED_BLOCKS + HG_BLOCKS, 256, DSMEM16P_BYTES>>>(pr, hg, PRED_BLOCKS);
        }
        // scores + softmax + alphas out
        k_escore<<<B, 256>>>(w_full_att, b_full_att, b_dec_att, b_enc_att, out, t);
        // awe fp16, gate sigmoid inline, writes gate*awe into x
        k_awe<<<dim3(E/512, B), 256>>>(b_fbeta);
        // x @ W_ih[640:] — precise fp16, S=8
        k_mma16p<<<dim3(G4/MM_BN, 1, XS), 256, DSMEM16P_BYTES>>>(ih);
        // gates reduce (embih + hh + x partials) + LSTM cell + masked carry
        k_lstm<<<(B*D)/256, 256>>>(b_hh, t);
    }
    // final preds(T-1) — plain fp16
    GP prF = {p_hnew, D, W_fc, V, out + (size_t)(T-1)*V, T*V, B, V, D,
              nullptr, 0, b_fc, p_declen, T-1, 0, PRED_BLOCKS};
    k_mma16<<<dim3(PRED_BLOCKS, 1, 1), 256, DSMEM16_BYTES>>>(prF);
}